// round 12
// baseline (speedup 1.0000x reference)
#include <cuda_runtime.h>
#include <cuda_fp16.h>
#include <cstdint>
#include <math.h>

#define NN 50000
#define NE 800000
#define F 64
#define KDIM 129      // 2*F + 1
#define K2 32         // 64 k's as 32 half2 pairs

#define SCAN_CHUNK 256
#define SCAN_NBLK ((NN + SCAN_CHUNK - 1) / SCAN_CHUNK)   // 196

#define NBLK  (148 * 3)   // persistent grid: pre kernel
#define FNBLK (148 * 4)   // persistent grid: fused layer kernel

// ---------------- scratch (static device globals — no allocation) ----------------
__device__ int    g_cnt[NN + 1];
__device__ int    g_rowptr[NN + 1];
__device__ int    g_rank[NE];
__device__ int    g_csr[NE];
__device__ int    g_bsum[SCAN_NBLK];
__device__ int    g_boff[SCAN_NBLK];
__device__ float  g_he[NN];
__device__ __align__(16) __half  g_p0[NN * F];
__device__ __align__(16) __half  g_q0[NN * F];
__device__ __align__(16) __half  g_p1[NN * F];
__device__ __align__(16) __half  g_q1[NN * F];
__device__ __align__(16) __half2 g_wt[6 * K2 * 128];   // [l][k2][n] half2 pairs
__device__ float2 g_p2[NN];
__device__ float2 g_q2[NN];

// ---------------- PTX helpers ----------------
__device__ __forceinline__ unsigned smem_u32(const void* p) {
    unsigned a;
    asm("{ .reg .u64 t; cvta.to.shared.u64 t, %1; cvt.u32.u64 %0, t; }" : "=r"(a) : "l"(p));
    return a;
}
#define CP_ASYNC4(dst_u32, src_ptr) \
    asm volatile("cp.async.ca.shared.global [%0], [%1], 4;" :: "r"(dst_u32), "l"(src_ptr))
#define CP_COMMIT() asm volatile("cp.async.commit_group;" ::: "memory")
#define CP_WAIT0()  asm volatile("cp.async.wait_group 0;" ::: "memory")
#define CP_WAIT1()  asm volatile("cp.async.wait_group 1;" ::: "memory")

// ---------------- prologue: CSR build ----------------
__global__ void hist_kernel(const float* __restrict__ ef, const int* __restrict__ dst) {
    int e = blockIdx.x * blockDim.x + threadIdx.x;
    if (e < NE) {
        int d = dst[e];
        g_rank[e] = atomicAdd(&g_cnt[d], 1);
        atomicAdd(&g_he[d], ef[e]);
    }
}

__device__ __forceinline__ int block_incl_scan(int v, int* smem) {
    const int t = threadIdx.x, lane = t & 31, w = t >> 5;
    int incl = v;
    #pragma unroll
    for (int off = 1; off < 32; off <<= 1) {
        int n = __shfl_up_sync(0xffffffffu, incl, off);
        if (lane >= off) incl += n;
    }
    if (lane == 31) smem[w] = incl;
    __syncthreads();
    if (w == 0) {
        int s = (lane < 8) ? smem[lane] : 0;
        #pragma unroll
        for (int off = 1; off < 8; off <<= 1) {
            int n = __shfl_up_sync(0xffffffffu, s, off);
            if (lane >= off) s += n;
        }
        if (lane < 8) smem[lane] = s;
    }
    __syncthreads();
    if (w > 0) incl += smem[w - 1];
    return incl;
}

__global__ void __launch_bounds__(256) scan1_kernel() {
    __shared__ int smem[8];
    int i = blockIdx.x * SCAN_CHUNK + threadIdx.x;
    int v = (i < NN) ? g_cnt[i] : 0;
    int incl = block_incl_scan(v, smem);
    if (threadIdx.x == 255) g_bsum[blockIdx.x] = incl;
}

__global__ void __launch_bounds__(256) scan2_kernel() {
    __shared__ int smem[8];
    int t = threadIdx.x;
    int v = (t < SCAN_NBLK) ? g_bsum[t] : 0;
    int incl = block_incl_scan(v, smem);
    if (t < SCAN_NBLK) g_boff[t] = incl - v;
    if (t == SCAN_NBLK - 1) g_rowptr[NN] = incl;
}

__global__ void __launch_bounds__(256) scan3_kernel() {
    __shared__ int smem[8];
    int i = blockIdx.x * SCAN_CHUNK + threadIdx.x;
    int v = (i < NN) ? g_cnt[i] : 0;
    int incl = block_incl_scan(v, smem);
    if (i < NN) g_rowptr[i] = g_boff[blockIdx.x] + incl - v;
}

__global__ void scatter_kernel(const int* __restrict__ src, const int* __restrict__ dst) {
    int e = blockIdx.x * blockDim.x + threadIdx.x;
    if (e < NE) {
        int d = dst[e];
        g_csr[g_rowptr[d] + g_rank[e]] = src[e];
    }
}

// ---------------- weight repack ----------------
__global__ void convert_w_kernel(const float* __restrict__ W1, const float* __restrict__ Wmid) {
    int idx = blockIdx.x * blockDim.x + threadIdx.x;
    if (idx < 6 * K2 * 128) {
        int l = idx >> 12;
        int rem = idx & 4095;
        int k2 = rem >> 7;
        int n = rem & 127;
        const float* Wl = (l == 0) ? W1 : (Wmid + (l - 1) * F * KDIM);
        int k = 2 * k2;
        float v0, v1;
        if (n < F) { v0 = Wl[n * KDIM + k];            v1 = Wl[n * KDIM + k + 1]; }
        else       { v0 = Wl[(n - F) * KDIM + F + k];  v1 = Wl[(n - F) * KDIM + F + k + 1]; }
        g_wt[idx] = __floats2half2_rn(v0, v1);
    }
}

// ---------------- 2-node warp matvec (pre kernel only) ------------------------
__device__ __forceinline__ void warp_matvec2(
    const uint4* __restrict__ sW, unsigned h0u, unsigned h1u,
    int lane, int v0, int v1,
    __half* __restrict__ p_out, __half* __restrict__ q_out)
{
    float f0[4] = {0.f, 0.f, 0.f, 0.f};
    float f1[4] = {0.f, 0.f, 0.f, 0.f};

    #pragma unroll
    for (int chunk = 0; chunk < 2; chunk++) {
        __half2 a0[4], a1[4];
        #pragma unroll
        for (int j = 0; j < 4; j++) {
            a0[j] = __float2half2_rn(0.f);
            a1[j] = __float2half2_rn(0.f);
        }
        #pragma unroll
        for (int kk = 0; kk < 16; kk++) {
            const int k2 = chunk * 16 + kk;
            unsigned b0 = __shfl_sync(0xffffffffu, h0u, k2);
            unsigned b1 = __shfl_sync(0xffffffffu, h1u, k2);
            __half2 hb0 = *reinterpret_cast<__half2*>(&b0);
            __half2 hb1 = *reinterpret_cast<__half2*>(&b1);
            uint4 wv = sW[k2 * 32 + lane];
            __half2 w0 = *reinterpret_cast<__half2*>(&wv.x);
            __half2 w1 = *reinterpret_cast<__half2*>(&wv.y);
            __half2 w2 = *reinterpret_cast<__half2*>(&wv.z);
            __half2 w3 = *reinterpret_cast<__half2*>(&wv.w);
            a0[0] = __hfma2(hb0, w0, a0[0]);
            a0[1] = __hfma2(hb0, w1, a0[1]);
            a0[2] = __hfma2(hb0, w2, a0[2]);
            a0[3] = __hfma2(hb0, w3, a0[3]);
            a1[0] = __hfma2(hb1, w0, a1[0]);
            a1[1] = __hfma2(hb1, w1, a1[1]);
            a1[2] = __hfma2(hb1, w2, a1[2]);
            a1[3] = __hfma2(hb1, w3, a1[3]);
        }
        #pragma unroll
        for (int j = 0; j < 4; j++) {
            float2 t0 = __half22float2(a0[j]);
            float2 t1 = __half22float2(a1[j]);
            f0[j] += t0.x + t0.y;
            f1[j] += t1.x + t1.y;
        }
    }

    __half2 oA0 = __floats2half2_rn(f0[0], f0[1]);
    __half2 oB0 = __floats2half2_rn(f0[2], f0[3]);
    __half2 oA1 = __floats2half2_rn(f1[0], f1[1]);
    __half2 oB1 = __floats2half2_rn(f1[2], f1[3]);
    uint2 u0, u1;
    u0.x = *reinterpret_cast<unsigned*>(&oA0);
    u0.y = *reinterpret_cast<unsigned*>(&oB0);
    u1.x = *reinterpret_cast<unsigned*>(&oA1);
    u1.y = *reinterpret_cast<unsigned*>(&oB1);
    if (lane < 16) {
        *reinterpret_cast<uint2*>(p_out + v0 * F + 4 * lane) = u0;
        *reinterpret_cast<uint2*>(p_out + v1 * F + 4 * lane) = u1;
    } else {
        *reinterpret_cast<uint2*>(q_out + v0 * F + 4 * (lane - 16)) = u0;
        *reinterpret_cast<uint2*>(q_out + v1 * F + 4 * (lane - 16)) = u1;
    }
}

// single-node gather (sigmoid/out kernel)
__device__ __forceinline__ float2 warp_agg(
    const __half* __restrict__ p_in, const __half* __restrict__ q_in,
    int v, int c0, float whe0, float whe1, float b0, float b1)
{
    const float he = g_he[v];
    float2 p = __half22float2(*reinterpret_cast<const __half2*>(p_in + v * F + c0));
    float acc0 = p.x + b0 + whe0 * he;
    float acc1 = p.y + b1 + whe1 * he;

    int j = g_rowptr[v];
    const int je = g_rowptr[v + 1];
    for (; j + 8 <= je; j += 8) {
        int idx[8];
        #pragma unroll
        for (int u = 0; u < 8; u++) idx[u] = g_csr[j + u];
        float2 f[8];
        #pragma unroll
        for (int u = 0; u < 8; u++)
            f[u] = __half22float2(*reinterpret_cast<const __half2*>(q_in + idx[u] * F + c0));
        #pragma unroll
        for (int u = 0; u < 8; u++) { acc0 += f[u].x; acc1 += f[u].y; }
    }
    for (; j < je; j++) {
        float2 f = __half22float2(*reinterpret_cast<const __half2*>(q_in + g_csr[j] * F + c0));
        acc0 += f.x;
        acc1 += f.y;
    }
    return make_float2(acc0, acc1);
}

// ---------------- pre: PQ1[v] = W1eff . node_feat[v] --------------------------
__global__ void __launch_bounds__(256) pre_kernel(
    const float* __restrict__ x,
    const __half2* __restrict__ wt,
    __half* __restrict__ p_out, __half* __restrict__ q_out)
{
    __shared__ uint4 sW[K2 * 32];
    const int tid = threadIdx.x;
    for (int i = tid; i < K2 * 32; i += 256)
        sW[i] = reinterpret_cast<const uint4*>(wt)[i];
    __syncthreads();

    const int lane = tid & 31;
    const int gwarp = (blockIdx.x * 256 + tid) >> 5;
    const int nwarps = (NBLK * 256) >> 5;

    for (int pp = gwarp; pp < NN / 2; pp += nwarps) {
        const int v0 = 2 * pp, v1 = v0 + 1;
        float2 x0 = *reinterpret_cast<const float2*>(x + v0 * F + 2 * lane);
        float2 x1 = *reinterpret_cast<const float2*>(x + v1 * F + 2 * lane);
        __half2 h0 = __floats2half2_rn(x0.x, x0.y);
        __half2 h1 = __floats2half2_rn(x1.x, x1.y);
        warp_matvec2(sW, *reinterpret_cast<unsigned*>(&h0),
                     *reinterpret_cast<unsigned*>(&h1), lane, v0, v1, p_out, q_out);
    }
}

// ---------------- fused layer, cp.async gather + 4-node matvec ----------------
// warp handles 4 consecutive nodes; gathered Q rows staged via cp.async.
__global__ void __launch_bounds__(256, 4) fused4_kernel(
    const __half* __restrict__ p_in, const __half* __restrict__ q_in,
    const float* __restrict__ Wcur,
    const float* __restrict__ bias,
    const __half2* __restrict__ wt_next,
    __half* __restrict__ p_out, __half* __restrict__ q_out)
{
    __shared__ uint4    sW[K2 * 32];        // 16 KB  W^T for next layer
    __shared__ uint4    sH[8][32];          // 4 KB   h broadcast (4 nodes packed)
    __shared__ unsigned sQ[8][2][8][32];    // 16 KB  staged Q rows (2 bufs x 8 edges)
    __shared__ int      sIdx[8][96];        // 3 KB   staged edge indices
    __shared__ float2   sAcc[8][4][32];     // 8 KB   per-node gather partials

    const int tid = threadIdx.x;
    for (int i = tid; i < K2 * 32; i += 256)
        sW[i] = reinterpret_cast<const uint4*>(wt_next)[i];
    __syncthreads();

    const int lane = tid & 31;
    const int w = tid >> 5;
    const int c0 = 2 * lane;
    const float whe0 = Wcur[(c0 + 0) * KDIM + 128];
    const float whe1 = Wcur[(c0 + 1) * KDIM + 128];
    const float b0 = bias[c0 + 0];
    const float b1 = bias[c0 + 1];

    const unsigned sQbase = smem_u32(&sQ[w][0][0][0]);
    const unsigned sIbase = smem_u32(&sIdx[w][0]);

    const int gwarp = (blockIdx.x * 256 + tid) >> 5;
    const int nwarps = (gridDim.x * 256) >> 5;

    for (int g = gwarp; g < NN / 4; g += nwarps) {
        const int v0 = 4 * g;

        int rv = 0;
        if (lane <= 4) rv = g_rowptr[v0 + lane];
        const int r0 = __shfl_sync(0xffffffffu, rv, 0);
        const int r4 = __shfl_sync(0xffffffffu, rv, 4);
        const int tot = r4 - r0;

        float a0 = 0.f, a1 = 0.f;
        int n = 0;
        int rnext = __shfl_sync(0xffffffffu, rv, 1) - r0;   // relative boundary

        if (tot > 0 && tot <= 96) {
            // stage indices
            for (int t = lane; t < tot; t += 32)
                CP_ASYNC4(sIbase + 4u * t, g_csr + r0 + t);
            CP_COMMIT();
            CP_WAIT0();
            __syncwarp();

            const int nc = (tot + 7) >> 3;
            // prime chunks 0 and 1
            {
                const int m = (tot < 8) ? tot : 8;
                for (int e = 0; e < 8; e++) if (e < m) {
                    int idx = sIdx[w][e];
                    CP_ASYNC4(sQbase + (unsigned)((e << 7) + (lane << 2)),
                              (const char*)q_in + ((size_t)idx << 7) + (lane << 2));
                }
                CP_COMMIT();
            }
            if (nc > 1) {
                const int m = (tot - 8 < 8) ? tot - 8 : 8;
                for (int e = 0; e < 8; e++) if (e < m) {
                    int idx = sIdx[w][8 + e];
                    CP_ASYNC4(sQbase + (unsigned)(((8 + e) << 7) + (lane << 2)),
                              (const char*)q_in + ((size_t)idx << 7) + (lane << 2));
                }
                CP_COMMIT();
            }

            for (int c = 0; c < nc; c++) {
                if (c + 1 < nc) { CP_WAIT1(); } else { CP_WAIT0(); }
                const int base = c * 8;
                const int m = (tot - base < 8) ? tot - base : 8;
                const int buf = c & 1;
                for (int e = 0; e < m; e++) {
                    const int jg = base + e;
                    if (jg >= rnext) {                       // uniform
                        do {
                            sAcc[w][n][lane] = make_float2(a0, a1);
                            a0 = 0.f; a1 = 0.f;
                            n++;
                            rnext = __shfl_sync(0xffffffffu, rv, n + 1) - r0;
                        } while (jg >= rnext && n < 3);
                    }
                    unsigned uq = sQ[w][buf][e][lane];
                    __half2 qh = *reinterpret_cast<__half2*>(&uq);
                    float2 f = __half22float2(qh);
                    a0 += f.x;
                    a1 += f.y;
                }
                if (c + 2 < nc) {
                    const int nb = (c + 2) * 8;
                    const int mm = (tot - nb < 8) ? tot - nb : 8;
                    for (int e = 0; e < 8; e++) if (e < mm) {
                        int idx = sIdx[w][nb + e];
                        CP_ASYNC4(sQbase + (unsigned)((((buf * 8) + e) << 7) + (lane << 2)),
                                  (const char*)q_in + ((size_t)idx << 7) + (lane << 2));
                    }
                    CP_COMMIT();
                }
            }
        } else if (tot > 96) {
            // rare fallback: direct gather
            for (int jg = 0; jg < tot; jg++) {
                if (jg >= rnext) {
                    do {
                        sAcc[w][n][lane] = make_float2(a0, a1);
                        a0 = 0.f; a1 = 0.f;
                        n++;
                        rnext = __shfl_sync(0xffffffffu, rv, n + 1) - r0;
                    } while (jg >= rnext && n < 3);
                }
                int idx = g_csr[r0 + jg];
                float2 f = __half22float2(*reinterpret_cast<const __half2*>(q_in + idx * F + c0));
                a0 += f.x;
                a1 += f.y;
            }
        }
        // flush current node + any trailing empty nodes
        sAcc[w][n][lane] = make_float2(a0, a1);
        for (int nn = n + 1; nn < 4; nn++) sAcc[w][nn][lane] = make_float2(0.f, 0.f);

        // combine with self/he/bias, relu, pack h for 4 nodes
        unsigned hh[4];
        #pragma unroll
        for (int nn = 0; nn < 4; nn++) {
            float2 pv = __half22float2(*reinterpret_cast<const __half2*>(p_in + (v0 + nn) * F + c0));
            float hev = g_he[v0 + nn];
            float2 s = sAcc[w][nn][lane];
            float x0 = fmaxf(s.x + pv.x + b0 + whe0 * hev, 0.f);
            float x1 = fmaxf(s.y + pv.y + b1 + whe1 * hev, 0.f);
            __half2 hx = __floats2half2_rn(x0, x1);
            hh[nn] = *reinterpret_cast<unsigned*>(&hx);
        }
        __syncwarp();   // previous iteration's sH reads complete on all lanes
        {
            uint4 hv;
            hv.x = hh[0]; hv.y = hh[1]; hv.z = hh[2]; hv.w = hh[3];
            sH[w][lane] = hv;
        }
        __syncwarp();

        // matvec: 4 nodes x 4 outs, fp16 accumulation over all 32 k2
        __half2 acc2[4][4];
        #pragma unroll
        for (int nn = 0; nn < 4; nn++)
            #pragma unroll
            for (int j = 0; j < 4; j++) acc2[nn][j] = __float2half2_rn(0.f);

        #pragma unroll
        for (int kk = 0; kk < K2; kk++) {
            uint4 hb = sH[w][kk];                 // broadcast
            uint4 wv = sW[kk * 32 + lane];        // conflict-free
            __half2 w0 = *reinterpret_cast<__half2*>(&wv.x);
            __half2 w1 = *reinterpret_cast<__half2*>(&wv.y);
            __half2 w2 = *reinterpret_cast<__half2*>(&wv.z);
            __half2 w3 = *reinterpret_cast<__half2*>(&wv.w);
            __half2 h0 = *reinterpret_cast<__half2*>(&hb.x);
            __half2 h1 = *reinterpret_cast<__half2*>(&hb.y);
            __half2 h2 = *reinterpret_cast<__half2*>(&hb.z);
            __half2 h3 = *reinterpret_cast<__half2*>(&hb.w);
            acc2[0][0] = __hfma2(h0, w0, acc2[0][0]);
            acc2[0][1] = __hfma2(h0, w1, acc2[0][1]);
            acc2[0][2] = __hfma2(h0, w2, acc2[0][2]);
            acc2[0][3] = __hfma2(h0, w3, acc2[0][3]);
            acc2[1][0] = __hfma2(h1, w0, acc2[1][0]);
            acc2[1][1] = __hfma2(h1, w1, acc2[1][1]);
            acc2[1][2] = __hfma2(h1, w2, acc2[1][2]);
            acc2[1][3] = __hfma2(h1, w3, acc2[1][3]);
            acc2[2][0] = __hfma2(h2, w0, acc2[2][0]);
            acc2[2][1] = __hfma2(h2, w1, acc2[2][1]);
            acc2[2][2] = __hfma2(h2, w2, acc2[2][2]);
            acc2[2][3] = __hfma2(h2, w3, acc2[2][3]);
            acc2[3][0] = __hfma2(h3, w0, acc2[3][0]);
            acc2[3][1] = __hfma2(h3, w1, acc2[3][1]);
            acc2[3][2] = __hfma2(h3, w2, acc2[3][2]);
            acc2[3][3] = __hfma2(h3, w3, acc2[3][3]);
        }

        // epilogue: reduce half2 pairs, store 8 B per node
        #pragma unroll
        for (int nn = 0; nn < 4; nn++) {
            float2 fa = __half22float2(acc2[nn][0]);
            float2 fb = __half22float2(acc2[nn][1]);
            float2 fc = __half22float2(acc2[nn][2]);
            float2 fd = __half22float2(acc2[nn][3]);
            __half2 o0 = __floats2half2_rn(fa.x + fa.y, fb.x + fb.y);
            __half2 o1 = __floats2half2_rn(fc.x + fc.y, fd.x + fd.y);
            uint2 u;
            u.x = *reinterpret_cast<unsigned*>(&o0);
            u.y = *reinterpret_cast<unsigned*>(&o1);
            if (lane < 16)
                *reinterpret_cast<uint2*>(p_out + (v0 + nn) * F + 4 * lane) = u;
            else
                *reinterpret_cast<uint2*>(q_out + (v0 + nn) * F + 4 * (lane - 16)) = u;
        }
    }
}

// ---------------- last hidden (sigmoid) fused with out_pre --------------------
__global__ void __launch_bounds__(256) agg_sigm_out_kernel(
    const __half* __restrict__ p_in, const __half* __restrict__ q_in,
    const float* __restrict__ Wcur,
    const float* __restrict__ bias,
    const float* __restrict__ W2)
{
    const int v    = (blockIdx.x * blockDim.x + threadIdx.x) >> 5;
    const int lane = threadIdx.x & 31;
    if (v >= NN) return;

    const int c0 = 2 * lane;
    const float whe0 = Wcur[(c0 + 0) * KDIM + 128];
    const float whe1 = Wcur[(c0 + 1) * KDIM + 128];

    float2 a = warp_agg(p_in, q_in, v, c0, whe0, whe1, bias[c0], bias[c0 + 1]);
    const float h0 = 1.f / (1.f + __expf(-a.x));
    const float h1 = 1.f / (1.f + __expf(-a.y));

    float p0 = W2[c0] * h0 + W2[c0 + 1] * h1;
    float p1 = W2[KDIM + c0] * h0 + W2[KDIM + c0 + 1] * h1;
    float q0 = W2[64 + c0] * h0 + W2[64 + c0 + 1] * h1;
    float q1 = W2[KDIM + 64 + c0] * h0 + W2[KDIM + 64 + c0 + 1] * h1;

    #pragma unroll
    for (int off = 16; off > 0; off >>= 1) {
        p0 += __shfl_xor_sync(0xffffffffu, p0, off);
        p1 += __shfl_xor_sync(0xffffffffu, p1, off);
        q0 += __shfl_xor_sync(0xffffffffu, q0, off);
        q1 += __shfl_xor_sync(0xffffffffu, q1, off);
    }
    if (lane == 0) {
        g_p2[v] = make_float2(p0, p1);
        g_q2[v] = make_float2(q0, q1);
    }
}

// ---------------- final layer: edge-parallel q2 sum ---------------------------
__global__ void __launch_bounds__(256) out_agg_kernel(
    const float* __restrict__ W2,
    const float* __restrict__ b2,
    float* __restrict__ out)
{
    const int v    = (blockIdx.x * blockDim.x + threadIdx.x) >> 5;
    const int lane = threadIdx.x & 31;
    if (v >= NN) return;

    const int js = g_rowptr[v];
    const int je = g_rowptr[v + 1];
    float acc0 = 0.f, acc1 = 0.f;
    for (int j = js + lane; j < je; j += 32) {
        float2 q = g_q2[g_csr[j]];
        acc0 += q.x;
        acc1 += q.y;
    }
    #pragma unroll
    for (int off = 16; off > 0; off >>= 1) {
        acc0 += __shfl_xor_sync(0xffffffffu, acc0, off);
        acc1 += __shfl_xor_sync(0xffffffffu, acc1, off);
    }
    if (lane == 0) {
        float2 mine = g_p2[v];
        float he = g_he[v];
        out[v * 2 + 0] = mine.x + acc0 + W2[128]        * he + b2[0];
        out[v * 2 + 1] = mine.y + acc1 + W2[KDIM + 128] * he + b2[1];
    }
}

// ---------------- launch ----------------
extern "C" void kernel_launch(void* const* d_in, const int* in_sizes, int n_in,
                              void* d_out, int out_size)
{
    const float* node_feat = (const float*)d_in[0];
    const float* edge_feat = (const float*)d_in[1];
    const int*   src       = (const int*)  d_in[2];
    const int*   dst       = (const int*)  d_in[3];
    const float* W1        = (const float*)d_in[4];
    const float* b1        = (const float*)d_in[5];
    const float* Wmid      = (const float*)d_in[6];
    const float* bmid      = (const float*)d_in[7];
    const float* W2        = (const float*)d_in[8];
    const float* b2        = (const float*)d_in[9];
    float*       out       = (float*)d_out;

    __half *p0, *q0, *p1, *q1;
    __half2* wt;
    void *cnt_ptr, *he_ptr;
    cudaGetSymbolAddress((void**)&p0, g_p0);
    cudaGetSymbolAddress((void**)&q0, g_q0);
    cudaGetSymbolAddress((void**)&p1, g_p1);
    cudaGetSymbolAddress((void**)&q1, g_q1);
    cudaGetSymbolAddress((void**)&wt, g_wt);
    cudaGetSymbolAddress(&cnt_ptr, g_cnt);
    cudaGetSymbolAddress(&he_ptr,  g_he);

    cudaMemsetAsync(cnt_ptr, 0, (NN + 1) * sizeof(int));
    cudaMemsetAsync(he_ptr,  0, NN * sizeof(float));
    hist_kernel<<<(NE + 255) / 256, 256>>>(edge_feat, dst);
    convert_w_kernel<<<(6 * K2 * 128 + 255) / 256, 256>>>(W1, Wmid);
    scan1_kernel<<<SCAN_NBLK, 256>>>();
    scan2_kernel<<<1, 256>>>();
    scan3_kernel<<<SCAN_NBLK, 256>>>();
    scatter_kernel<<<(NE + 255) / 256, 256>>>(src, dst);

    const int WPN_GRID = (NN * 32 + 255) / 256;   // 6250

    pre_kernel<<<NBLK, 256>>>(node_feat, wt + 0 * K2 * 128, p0, q0);
    fused4_kernel<<<FNBLK, 256>>>(p0, q0, W1, b1, wt + 1 * K2 * 128, p1, q1);
    fused4_kernel<<<FNBLK, 256>>>(p1, q1, Wmid + 0 * F * KDIM, bmid + 0 * F, wt + 2 * K2 * 128, p0, q0);
    fused4_kernel<<<FNBLK, 256>>>(p0, q0, Wmid + 1 * F * KDIM, bmid + 1 * F, wt + 3 * K2 * 128, p1, q1);
    fused4_kernel<<<FNBLK, 256>>>(p1, q1, Wmid + 2 * F * KDIM, bmid + 2 * F, wt + 4 * K2 * 128, p0, q0);
    fused4_kernel<<<FNBLK, 256>>>(p0, q0, Wmid + 3 * F * KDIM, bmid + 3 * F, wt + 5 * K2 * 128, p1, q1);
    agg_sigm_out_kernel<<<WPN_GRID, 256>>>(p1, q1, Wmid + 4 * F * KDIM, bmid + 4 * F, W2);
    out_agg_kernel<<<WPN_GRID, 256>>>(W2, b2, out);
}

// round 15
// speedup vs baseline: 1.2321x; 1.2321x over previous
#include <cuda_runtime.h>
#include <cuda_fp16.h>
#include <cstdint>
#include <math.h>

#define NN 50000
#define NE 800000
#define F 64
#define KDIM 129      // 2*F + 1
#define K2 32         // 64 k's as 32 half2 pairs

#define SCAN_CHUNK 256
#define SCAN_NBLK ((NN + SCAN_CHUNK - 1) / SCAN_CHUNK)   // 196

#define NBLK (148 * 3)   // persistent grid for fused layer kernels

// ---------------- scratch (static device globals — no allocation) ----------------
__device__ int    g_cnt[NN + 1];
__device__ int    g_rowptr[NN + 1];
__device__ int    g_rank[NE];
__device__ int    g_csr[NE];
__device__ int    g_bsum[SCAN_NBLK];
__device__ int    g_boff[SCAN_NBLK];
__device__ float  g_he[NN];
__device__ __align__(16) __half  g_p0[NN * F];
__device__ __align__(16) __half  g_q0[NN * F];
__device__ __align__(16) __half  g_p1[NN * F];
__device__ __align__(16) __half  g_q1[NN * F];
__device__ __align__(16) __half2 g_wt[6 * K2 * 128];   // [l][k2][n] half2 pairs
__device__ float2 g_p2[NN];
__device__ float2 g_q2[NN];

// ---------------- prologue: CSR build ----------------
__global__ void hist_kernel(const float* __restrict__ ef, const int* __restrict__ dst) {
    int e = blockIdx.x * blockDim.x + threadIdx.x;
    if (e < NE) {
        int d = dst[e];
        g_rank[e] = atomicAdd(&g_cnt[d], 1);
        atomicAdd(&g_he[d], ef[e]);
    }
}

__device__ __forceinline__ int block_incl_scan(int v, int* smem) {
    const int t = threadIdx.x, lane = t & 31, w = t >> 5;
    int incl = v;
    #pragma unroll
    for (int off = 1; off < 32; off <<= 1) {
        int n = __shfl_up_sync(0xffffffffu, incl, off);
        if (lane >= off) incl += n;
    }
    if (lane == 31) smem[w] = incl;
    __syncthreads();
    if (w == 0) {
        int s = (lane < 8) ? smem[lane] : 0;
        #pragma unroll
        for (int off = 1; off < 8; off <<= 1) {
            int n = __shfl_up_sync(0xffffffffu, s, off);
            if (lane >= off) s += n;
        }
        if (lane < 8) smem[lane] = s;
    }
    __syncthreads();
    if (w > 0) incl += smem[w - 1];
    return incl;
}

__global__ void __launch_bounds__(256) scan1_kernel() {
    __shared__ int smem[8];
    int i = blockIdx.x * SCAN_CHUNK + threadIdx.x;
    int v = (i < NN) ? g_cnt[i] : 0;
    int incl = block_incl_scan(v, smem);
    if (threadIdx.x == 255) g_bsum[blockIdx.x] = incl;
}

__global__ void __launch_bounds__(256) scan2_kernel() {
    __shared__ int smem[8];
    int t = threadIdx.x;
    int v = (t < SCAN_NBLK) ? g_bsum[t] : 0;
    int incl = block_incl_scan(v, smem);
    if (t < SCAN_NBLK) g_boff[t] = incl - v;
    if (t == SCAN_NBLK - 1) g_rowptr[NN] = incl;
}

__global__ void __launch_bounds__(256) scan3_kernel() {
    __shared__ int smem[8];
    int i = blockIdx.x * SCAN_CHUNK + threadIdx.x;
    int v = (i < NN) ? g_cnt[i] : 0;
    int incl = block_incl_scan(v, smem);
    if (i < NN) g_rowptr[i] = g_boff[blockIdx.x] + incl - v;
}

__global__ void scatter_kernel(const int* __restrict__ src, const int* __restrict__ dst) {
    int e = blockIdx.x * blockDim.x + threadIdx.x;
    if (e < NE) {
        int d = dst[e];
        g_csr[g_rowptr[d] + g_rank[e]] = src[e];
    }
}

// ---------------- weight repack ----------------
__global__ void convert_w_kernel(const float* __restrict__ W1, const float* __restrict__ Wmid) {
    int idx = blockIdx.x * blockDim.x + threadIdx.x;
    if (idx < 6 * K2 * 128) {
        int l = idx >> 12;
        int rem = idx & 4095;
        int k2 = rem >> 7;
        int n = rem & 127;
        const float* Wl = (l == 0) ? W1 : (Wmid + (l - 1) * F * KDIM);
        int k = 2 * k2;
        float v0, v1;
        if (n < F) { v0 = Wl[n * KDIM + k];            v1 = Wl[n * KDIM + k + 1]; }
        else       { v0 = Wl[(n - F) * KDIM + F + k];  v1 = Wl[(n - F) * KDIM + F + k + 1]; }
        g_wt[idx] = __floats2half2_rn(v0, v1);
    }
}

// ---------------- warp matvec (pair): smem h broadcast, pure fp16 accum ------
// sH: per-warp staging (uint2 per lane). sW: uint4[K2][32].
__device__ __forceinline__ void warp_matvec2s(
    const uint4* __restrict__ sW, uint2* __restrict__ sHw,
    unsigned h0u, unsigned h1u,
    int lane, int v0, int v1,
    __half* __restrict__ p_out, __half* __restrict__ q_out)
{
    __syncwarp();
    sHw[lane] = make_uint2(h0u, h1u);
    __syncwarp();

    __half2 a0[4], a1[4];
    #pragma unroll
    for (int j = 0; j < 4; j++) {
        a0[j] = __float2half2_rn(0.f);
        a1[j] = __float2half2_rn(0.f);
    }

    #pragma unroll
    for (int k2 = 0; k2 < K2; k2++) {
        uint2 hb = sHw[k2];                     // broadcast LDS.64
        __half2 hb0 = *reinterpret_cast<__half2*>(&hb.x);
        __half2 hb1 = *reinterpret_cast<__half2*>(&hb.y);
        uint4 wv = sW[k2 * 32 + lane];          // conflict-free LDS.128
        __half2 w0 = *reinterpret_cast<__half2*>(&wv.x);
        __half2 w1 = *reinterpret_cast<__half2*>(&wv.y);
        __half2 w2 = *reinterpret_cast<__half2*>(&wv.z);
        __half2 w3 = *reinterpret_cast<__half2*>(&wv.w);
        a0[0] = __hfma2(hb0, w0, a0[0]);
        a0[1] = __hfma2(hb0, w1, a0[1]);
        a0[2] = __hfma2(hb0, w2, a0[2]);
        a0[3] = __hfma2(hb0, w3, a0[3]);
        a1[0] = __hfma2(hb1, w0, a1[0]);
        a1[1] = __hfma2(hb1, w1, a1[1]);
        a1[2] = __hfma2(hb1, w2, a1[2]);
        a1[3] = __hfma2(hb1, w3, a1[3]);
    }

    float2 fa0 = __half22float2(a0[0]);
    float2 fb0 = __half22float2(a0[1]);
    float2 fc0 = __half22float2(a0[2]);
    float2 fd0 = __half22float2(a0[3]);
    float2 fa1 = __half22float2(a1[0]);
    float2 fb1 = __half22float2(a1[1]);
    float2 fc1 = __half22float2(a1[2]);
    float2 fd1 = __half22float2(a1[3]);
    __half2 o00 = __floats2half2_rn(fa0.x + fa0.y, fb0.x + fb0.y);
    __half2 o01 = __floats2half2_rn(fc0.x + fc0.y, fd0.x + fd0.y);
    __half2 o10 = __floats2half2_rn(fa1.x + fa1.y, fb1.x + fb1.y);
    __half2 o11 = __floats2half2_rn(fc1.x + fc1.y, fd1.x + fd1.y);
    uint2 u0, u1;
    u0.x = *reinterpret_cast<unsigned*>(&o00);
    u0.y = *reinterpret_cast<unsigned*>(&o01);
    u1.x = *reinterpret_cast<unsigned*>(&o10);
    u1.y = *reinterpret_cast<unsigned*>(&o11);
    if (lane < 16) {
        *reinterpret_cast<uint2*>(p_out + v0 * F + 4 * lane) = u0;
        *reinterpret_cast<uint2*>(p_out + v1 * F + 4 * lane) = u1;
    } else {
        *reinterpret_cast<uint2*>(q_out + v0 * F + 4 * (lane - 16)) = u0;
        *reinterpret_cast<uint2*>(q_out + v1 * F + 4 * (lane - 16)) = u1;
    }
}

// ---------------- interleaved dual-node gather (MLP 16) -----------------------
__device__ __forceinline__ float4 warp_agg2(
    const __half* __restrict__ p_in, const __half* __restrict__ q_in,
    int v0, int v1, int c0, float whe0, float whe1, float b0, float b1)
{
    const float heA = g_he[v0];
    const float heB = g_he[v1];
    float2 pA = __half22float2(*reinterpret_cast<const __half2*>(p_in + v0 * F + c0));
    float2 pB = __half22float2(*reinterpret_cast<const __half2*>(p_in + v1 * F + c0));
    float a0 = pA.x + b0 + whe0 * heA;
    float a1 = pA.y + b1 + whe1 * heA;
    float a2 = pB.x + b0 + whe0 * heB;
    float a3 = pB.y + b1 + whe1 * heB;

    int j0 = g_rowptr[v0];
    const int e0 = g_rowptr[v0 + 1];
    int j1 = g_rowptr[v1];
    const int e1 = g_rowptr[v1 + 1];

    while (j0 + 8 <= e0 && j1 + 8 <= e1) {
        int i0[8], i1[8];
        #pragma unroll
        for (int u = 0; u < 8; u++) i0[u] = g_csr[j0 + u];
        #pragma unroll
        for (int u = 0; u < 8; u++) i1[u] = g_csr[j1 + u];
        float2 f0[8], f1[8];
        #pragma unroll
        for (int u = 0; u < 8; u++)
            f0[u] = __half22float2(*reinterpret_cast<const __half2*>(q_in + i0[u] * F + c0));
        #pragma unroll
        for (int u = 0; u < 8; u++)
            f1[u] = __half22float2(*reinterpret_cast<const __half2*>(q_in + i1[u] * F + c0));
        #pragma unroll
        for (int u = 0; u < 8; u++) { a0 += f0[u].x; a1 += f0[u].y; }
        #pragma unroll
        for (int u = 0; u < 8; u++) { a2 += f1[u].x; a3 += f1[u].y; }
        j0 += 8;
        j1 += 8;
    }
    for (; j0 + 8 <= e0; j0 += 8) {
        int i0[8];
        #pragma unroll
        for (int u = 0; u < 8; u++) i0[u] = g_csr[j0 + u];
        float2 f0[8];
        #pragma unroll
        for (int u = 0; u < 8; u++)
            f0[u] = __half22float2(*reinterpret_cast<const __half2*>(q_in + i0[u] * F + c0));
        #pragma unroll
        for (int u = 0; u < 8; u++) { a0 += f0[u].x; a1 += f0[u].y; }
    }
    for (; j0 < e0; j0++) {
        float2 f = __half22float2(*reinterpret_cast<const __half2*>(q_in + g_csr[j0] * F + c0));
        a0 += f.x;
        a1 += f.y;
    }
    for (; j1 + 8 <= e1; j1 += 8) {
        int i1[8];
        #pragma unroll
        for (int u = 0; u < 8; u++) i1[u] = g_csr[j1 + u];
        float2 f1[8];
        #pragma unroll
        for (int u = 0; u < 8; u++)
            f1[u] = __half22float2(*reinterpret_cast<const __half2*>(q_in + i1[u] * F + c0));
        #pragma unroll
        for (int u = 0; u < 8; u++) { a2 += f1[u].x; a3 += f1[u].y; }
    }
    for (; j1 < e1; j1++) {
        float2 f = __half22float2(*reinterpret_cast<const __half2*>(q_in + g_csr[j1] * F + c0));
        a2 += f.x;
        a3 += f.y;
    }
    return make_float4(a0, a1, a2, a3);
}

// single-node gather (sigmoid/out kernel)
__device__ __forceinline__ float2 warp_agg(
    const __half* __restrict__ p_in, const __half* __restrict__ q_in,
    int v, int c0, float whe0, float whe1, float b0, float b1)
{
    const float he = g_he[v];
    float2 p = __half22float2(*reinterpret_cast<const __half2*>(p_in + v * F + c0));
    float acc0 = p.x + b0 + whe0 * he;
    float acc1 = p.y + b1 + whe1 * he;

    int j = g_rowptr[v];
    const int je = g_rowptr[v + 1];
    for (; j + 8 <= je; j += 8) {
        int idx[8];
        #pragma unroll
        for (int u = 0; u < 8; u++) idx[u] = g_csr[j + u];
        float2 f[8];
        #pragma unroll
        for (int u = 0; u < 8; u++)
            f[u] = __half22float2(*reinterpret_cast<const __half2*>(q_in + idx[u] * F + c0));
        #pragma unroll
        for (int u = 0; u < 8; u++) { acc0 += f[u].x; acc1 += f[u].y; }
    }
    for (; j < je; j++) {
        float2 f = __half22float2(*reinterpret_cast<const __half2*>(q_in + g_csr[j] * F + c0));
        acc0 += f.x;
        acc1 += f.y;
    }
    return make_float2(acc0, acc1);
}

// ---------------- pre: PQ1[v] = W1eff . node_feat[v] --------------------------
__global__ void __launch_bounds__(256) pre_kernel(
    const float* __restrict__ x,
    const __half2* __restrict__ wt,
    __half* __restrict__ p_out, __half* __restrict__ q_out)
{
    __shared__ uint4 sW[K2 * 32];
    __shared__ uint2 sH[8][32];
    const int tid = threadIdx.x;
    for (int i = tid; i < K2 * 32; i += 256)
        sW[i] = reinterpret_cast<const uint4*>(wt)[i];
    __syncthreads();

    const int lane = tid & 31;
    const int w = tid >> 5;
    const int gwarp = (blockIdx.x * 256 + tid) >> 5;
    const int nwarps = (NBLK * 256) >> 5;

    for (int pp = gwarp; pp < NN / 2; pp += nwarps) {
        const int v0 = 2 * pp, v1 = v0 + 1;
        float2 x0 = *reinterpret_cast<const float2*>(x + v0 * F + 2 * lane);
        float2 x1 = *reinterpret_cast<const float2*>(x + v1 * F + 2 * lane);
        __half2 h0 = __floats2half2_rn(x0.x, x0.y);
        __half2 h1 = __floats2half2_rn(x1.x, x1.y);
        warp_matvec2s(sW, sH[w], *reinterpret_cast<unsigned*>(&h0),
                      *reinterpret_cast<unsigned*>(&h1), lane, v0, v1, p_out, q_out);
    }
}

// ---------------- fused layer: h = relu(agg(PQ_in)); PQ_out = Wt_next . h -----
__global__ void __launch_bounds__(256) fused_kernel(
    const __half* __restrict__ p_in, const __half* __restrict__ q_in,
    const float* __restrict__ Wcur,
    const float* __restrict__ bias,
    const __half2* __restrict__ wt_next,
    __half* __restrict__ p_out, __half* __restrict__ q_out)
{
    __shared__ uint4 sW[K2 * 32];
    __shared__ uint2 sH[8][32];
    const int tid = threadIdx.x;
    for (int i = tid; i < K2 * 32; i += 256)
        sW[i] = reinterpret_cast<const uint4*>(wt_next)[i];
    __syncthreads();

    const int lane = tid & 31;
    const int w = tid >> 5;
    const int c0 = 2 * lane;
    const float whe0 = Wcur[(c0 + 0) * KDIM + 128];
    const float whe1 = Wcur[(c0 + 1) * KDIM + 128];
    const float b0 = bias[c0 + 0];
    const float b1 = bias[c0 + 1];

    const int gwarp = (blockIdx.x * 256 + tid) >> 5;
    const int nwarps = (NBLK * 256) >> 5;

    for (int pp = gwarp; pp < NN / 2; pp += nwarps) {
        const int v0 = 2 * pp, v1 = v0 + 1;
        float4 a = warp_agg2(p_in, q_in, v0, v1, c0, whe0, whe1, b0, b1);
        __half2 h0 = __floats2half2_rn(fmaxf(a.x, 0.f), fmaxf(a.y, 0.f));
        __half2 h1 = __floats2half2_rn(fmaxf(a.z, 0.f), fmaxf(a.w, 0.f));
        warp_matvec2s(sW, sH[w], *reinterpret_cast<unsigned*>(&h0),
                      *reinterpret_cast<unsigned*>(&h1), lane, v0, v1, p_out, q_out);
    }
}

// ---------------- last hidden (sigmoid) fused with out_pre --------------------
__global__ void __launch_bounds__(256) agg_sigm_out_kernel(
    const __half* __restrict__ p_in, const __half* __restrict__ q_in,
    const float* __restrict__ Wcur,
    const float* __restrict__ bias,
    const float* __restrict__ W2)
{
    const int v    = (blockIdx.x * blockDim.x + threadIdx.x) >> 5;
    const int lane = threadIdx.x & 31;
    if (v >= NN) return;

    const int c0 = 2 * lane;
    const float whe0 = Wcur[(c0 + 0) * KDIM + 128];
    const float whe1 = Wcur[(c0 + 1) * KDIM + 128];

    float2 a = warp_agg(p_in, q_in, v, c0, whe0, whe1, bias[c0], bias[c0 + 1]);
    const float h0 = 1.f / (1.f + __expf(-a.x));
    const float h1 = 1.f / (1.f + __expf(-a.y));

    float p0 = W2[c0] * h0 + W2[c0 + 1] * h1;
    float p1 = W2[KDIM + c0] * h0 + W2[KDIM + c0 + 1] * h1;
    float q0 = W2[64 + c0] * h0 + W2[64 + c0 + 1] * h1;
    float q1 = W2[KDIM + 64 + c0] * h0 + W2[KDIM + 64 + c0 + 1] * h1;

    #pragma unroll
    for (int off = 16; off > 0; off >>= 1) {
        p0 += __shfl_xor_sync(0xffffffffu, p0, off);
        p1 += __shfl_xor_sync(0xffffffffu, p1, off);
        q0 += __shfl_xor_sync(0xffffffffu, q0, off);
        q1 += __shfl_xor_sync(0xffffffffu, q1, off);
    }
    if (lane == 0) {
        g_p2[v] = make_float2(p0, p1);
        g_q2[v] = make_float2(q0, q1);
    }
}

// ---------------- final layer: edge-parallel q2 sum ---------------------------
__global__ void __launch_bounds__(256) out_agg_kernel(
    const float* __restrict__ W2,
    const float* __restrict__ b2,
    float* __restrict__ out)
{
    const int v    = (blockIdx.x * blockDim.x + threadIdx.x) >> 5;
    const int lane = threadIdx.x & 31;
    if (v >= NN) return;

    const int js = g_rowptr[v];
    const int je = g_rowptr[v + 1];
    float acc0 = 0.f, acc1 = 0.f;
    for (int j = js + lane; j < je; j += 32) {
        float2 q = g_q2[g_csr[j]];
        acc0 += q.x;
        acc1 += q.y;
    }
    #pragma unroll
    for (int off = 16; off > 0; off >>= 1) {
        acc0 += __shfl_xor_sync(0xffffffffu, acc0, off);
        acc1 += __shfl_xor_sync(0xffffffffu, acc1, off);
    }
    if (lane == 0) {
        float2 mine = g_p2[v];
        float he = g_he[v];
        out[v * 2 + 0] = mine.x + acc0 + W2[128]        * he + b2[0];
        out[v * 2 + 1] = mine.y + acc1 + W2[KDIM + 128] * he + b2[1];
    }
}

// ---------------- launch ----------------
extern "C" void kernel_launch(void* const* d_in, const int* in_sizes, int n_in,
                              void* d_out, int out_size)
{
    const float* node_feat = (const float*)d_in[0];
    const float* edge_feat = (const float*)d_in[1];
    const int*   src       = (const int*)  d_in[2];
    const int*   dst       = (const int*)  d_in[3];
    const float* W1        = (const float*)d_in[4];
    const float* b1        = (const float*)d_in[5];
    const float* Wmid      = (const float*)d_in[6];
    const float* bmid      = (const float*)d_in[7];
    const float* W2        = (const float*)d_in[8];
    const float* b2        = (const float*)d_in[9];
    float*       out       = (float*)d_out;

    __half *p0, *q0, *p1, *q1;
    __half2* wt;
    void *cnt_ptr, *he_ptr;
    cudaGetSymbolAddress((void**)&p0, g_p0);
    cudaGetSymbolAddress((void**)&q0, g_q0);
    cudaGetSymbolAddress((void**)&p1, g_p1);
    cudaGetSymbolAddress((void**)&q1, g_q1);
    cudaGetSymbolAddress((void**)&wt, g_wt);
    cudaGetSymbolAddress(&cnt_ptr, g_cnt);
    cudaGetSymbolAddress(&he_ptr,  g_he);

    cudaMemsetAsync(cnt_ptr, 0, (NN + 1) * sizeof(int));
    cudaMemsetAsync(he_ptr,  0, NN * sizeof(float));
    hist_kernel<<<(NE + 255) / 256, 256>>>(edge_feat, dst);
    convert_w_kernel<<<(6 * K2 * 128 + 255) / 256, 256>>>(W1, Wmid);
    scan1_kernel<<<SCAN_NBLK, 256>>>();
    scan2_kernel<<<1, 256>>>();
    scan3_kernel<<<SCAN_NBLK, 256>>>();
    scatter_kernel<<<(NE + 255) / 256, 256>>>(src, dst);

    const int WPN_GRID = (NN * 32 + 255) / 256;   // 6250

    pre_kernel<<<NBLK, 256>>>(node_feat, wt + 0 * K2 * 128, p0, q0);
    fused_kernel<<<NBLK, 256>>>(p0, q0, W1, b1, wt + 1 * K2 * 128, p1, q1);
    fused_kernel<<<NBLK, 256>>>(p1, q1, Wmid + 0 * F * KDIM, bmid + 0 * F, wt + 2 * K2 * 128, p0, q0);
    fused_kernel<<<NBLK, 256>>>(p0, q0, Wmid + 1 * F * KDIM, bmid + 1 * F, wt + 3 * K2 * 128, p1, q1);
    fused_kernel<<<NBLK, 256>>>(p1, q1, Wmid + 2 * F * KDIM, bmid + 2 * F, wt + 4 * K2 * 128, p0, q0);
    fused_kernel<<<NBLK, 256>>>(p0, q0, Wmid + 3 * F * KDIM, bmid + 3 * F, wt + 5 * K2 * 128, p1, q1);
    agg_sigm_out_kernel<<<WPN_GRID, 256>>>(p1, q1, Wmid + 4 * F * KDIM, bmid + 4 * F, W2);
    out_agg_kernel<<<WPN_GRID, 256>>>(W2, b2, out);
}

// round 16
// speedup vs baseline: 1.3032x; 1.0576x over previous
#include <cuda_runtime.h>
#include <cuda_fp16.h>
#include <cstdint>
#include <math.h>

#define NN 50000
#define NE 800000
#define F 64
#define KDIM 129      // 2*F + 1
#define K2 32         // 64 k's as 32 half2 pairs

#define SCAN_CHUNK 256
#define SCAN_NBLK ((NN + SCAN_CHUNK - 1) / SCAN_CHUNK)   // 196

#define NBLK  (148 * 3)   // persistent grid: pre kernel
#define FNBLK (148 * 4)   // persistent grid: fused kernels (4 blocks/SM)

// ---------------- scratch (static device globals — no allocation) ----------------
__device__ int    g_cnt[NN + 1];
__device__ int    g_rowptr[NN + 1];
__device__ int    g_rank[NE];
__device__ int    g_csr[NE];
__device__ int    g_bsum[SCAN_NBLK];
__device__ int    g_boff[SCAN_NBLK];
__device__ float  g_he[NN];
__device__ __align__(16) __half  g_p0[NN * F];
__device__ __align__(16) __half  g_q0[NN * F];
__device__ __align__(16) __half  g_p1[NN * F];
__device__ __align__(16) __half  g_q1[NN * F];
__device__ __align__(16) __half2 g_wt[6 * K2 * 128];   // [l][k2][n] half2 pairs
__device__ float2 g_p2[NN];
__device__ float2 g_q2[NN];

// ---------------- prologue: CSR build ----------------
__global__ void hist_kernel(const float* __restrict__ ef, const int* __restrict__ dst) {
    int e = blockIdx.x * blockDim.x + threadIdx.x;
    if (e < NE) {
        int d = dst[e];
        g_rank[e] = atomicAdd(&g_cnt[d], 1);
        atomicAdd(&g_he[d], ef[e]);
    }
}

__device__ __forceinline__ int block_incl_scan(int v, int* smem) {
    const int t = threadIdx.x, lane = t & 31, w = t >> 5;
    int incl = v;
    #pragma unroll
    for (int off = 1; off < 32; off <<= 1) {
        int n = __shfl_up_sync(0xffffffffu, incl, off);
        if (lane >= off) incl += n;
    }
    if (lane == 31) smem[w] = incl;
    __syncthreads();
    if (w == 0) {
        int s = (lane < 8) ? smem[lane] : 0;
        #pragma unroll
        for (int off = 1; off < 8; off <<= 1) {
            int n = __shfl_up_sync(0xffffffffu, s, off);
            if (lane >= off) s += n;
        }
        if (lane < 8) smem[lane] = s;
    }
    __syncthreads();
    if (w > 0) incl += smem[w - 1];
    return incl;
}

__global__ void __launch_bounds__(256) scan1_kernel() {
    __shared__ int smem[8];
    int i = blockIdx.x * SCAN_CHUNK + threadIdx.x;
    int v = (i < NN) ? g_cnt[i] : 0;
    int incl = block_incl_scan(v, smem);
    if (threadIdx.x == 255) g_bsum[blockIdx.x] = incl;
}

__global__ void __launch_bounds__(256) scan2_kernel() {
    __shared__ int smem[8];
    int t = threadIdx.x;
    int v = (t < SCAN_NBLK) ? g_bsum[t] : 0;
    int incl = block_incl_scan(v, smem);
    if (t < SCAN_NBLK) g_boff[t] = incl - v;
    if (t == SCAN_NBLK - 1) g_rowptr[NN] = incl;
}

__global__ void __launch_bounds__(256) scan3_kernel() {
    __shared__ int smem[8];
    int i = blockIdx.x * SCAN_CHUNK + threadIdx.x;
    int v = (i < NN) ? g_cnt[i] : 0;
    int incl = block_incl_scan(v, smem);
    if (i < NN) g_rowptr[i] = g_boff[blockIdx.x] + incl - v;
}

__global__ void scatter_kernel(const int* __restrict__ src, const int* __restrict__ dst) {
    int e = blockIdx.x * blockDim.x + threadIdx.x;
    if (e < NE) {
        int d = dst[e];
        g_csr[g_rowptr[d] + g_rank[e]] = src[e];
    }
}

// ---------------- weight repack ----------------
__global__ void convert_w_kernel(const float* __restrict__ W1, const float* __restrict__ Wmid) {
    int idx = blockIdx.x * blockDim.x + threadIdx.x;
    if (idx < 6 * K2 * 128) {
        int l = idx >> 12;
        int rem = idx & 4095;
        int k2 = rem >> 7;
        int n = rem & 127;
        const float* Wl = (l == 0) ? W1 : (Wmid + (l - 1) * F * KDIM);
        int k = 2 * k2;
        float v0, v1;
        if (n < F) { v0 = Wl[n * KDIM + k];            v1 = Wl[n * KDIM + k + 1]; }
        else       { v0 = Wl[(n - F) * KDIM + F + k];  v1 = Wl[(n - F) * KDIM + F + k + 1]; }
        g_wt[idx] = __floats2half2_rn(v0, v1);
    }
}

// ---------------- warp matvec (R11 proven form): SHFL broadcast --------------
__device__ __forceinline__ void warp_matvec2(
    const uint4* __restrict__ sW, unsigned h0u, unsigned h1u,
    int lane, int v0, int v1,
    __half* __restrict__ p_out, __half* __restrict__ q_out)
{
    float f0[4] = {0.f, 0.f, 0.f, 0.f};
    float f1[4] = {0.f, 0.f, 0.f, 0.f};

    #pragma unroll
    for (int chunk = 0; chunk < 2; chunk++) {
        __half2 a0[4], a1[4];
        #pragma unroll
        for (int j = 0; j < 4; j++) {
            a0[j] = __float2half2_rn(0.f);
            a1[j] = __float2half2_rn(0.f);
        }
        #pragma unroll
        for (int kk = 0; kk < 16; kk++) {
            const int k2 = chunk * 16 + kk;
            unsigned b0 = __shfl_sync(0xffffffffu, h0u, k2);
            unsigned b1 = __shfl_sync(0xffffffffu, h1u, k2);
            __half2 hb0 = *reinterpret_cast<__half2*>(&b0);
            __half2 hb1 = *reinterpret_cast<__half2*>(&b1);
            uint4 wv = sW[k2 * 32 + lane];
            __half2 w0 = *reinterpret_cast<__half2*>(&wv.x);
            __half2 w1 = *reinterpret_cast<__half2*>(&wv.y);
            __half2 w2 = *reinterpret_cast<__half2*>(&wv.z);
            __half2 w3 = *reinterpret_cast<__half2*>(&wv.w);
            a0[0] = __hfma2(hb0, w0, a0[0]);
            a0[1] = __hfma2(hb0, w1, a0[1]);
            a0[2] = __hfma2(hb0, w2, a0[2]);
            a0[3] = __hfma2(hb0, w3, a0[3]);
            a1[0] = __hfma2(hb1, w0, a1[0]);
            a1[1] = __hfma2(hb1, w1, a1[1]);
            a1[2] = __hfma2(hb1, w2, a1[2]);
            a1[3] = __hfma2(hb1, w3, a1[3]);
        }
        #pragma unroll
        for (int j = 0; j < 4; j++) {
            float2 t0 = __half22float2(a0[j]);
            float2 t1 = __half22float2(a1[j]);
            f0[j] += t0.x + t0.y;
            f1[j] += t1.x + t1.y;
        }
    }

    __half2 oA0 = __floats2half2_rn(f0[0], f0[1]);
    __half2 oB0 = __floats2half2_rn(f0[2], f0[3]);
    __half2 oA1 = __floats2half2_rn(f1[0], f1[1]);
    __half2 oB1 = __floats2half2_rn(f1[2], f1[3]);
    uint2 u0, u1;
    u0.x = *reinterpret_cast<unsigned*>(&oA0);
    u0.y = *reinterpret_cast<unsigned*>(&oB0);
    u1.x = *reinterpret_cast<unsigned*>(&oA1);
    u1.y = *reinterpret_cast<unsigned*>(&oB1);
    if (lane < 16) {
        *reinterpret_cast<uint2*>(p_out + v0 * F + 4 * lane) = u0;
        *reinterpret_cast<uint2*>(p_out + v1 * F + 4 * lane) = u1;
    } else {
        *reinterpret_cast<uint2*>(q_out + v0 * F + 4 * (lane - 16)) = u0;
        *reinterpret_cast<uint2*>(q_out + v1 * F + 4 * (lane - 16)) = u1;
    }
}

// ---------------- interleaved dual-node gather, 4+4 (low-reg) -----------------
__device__ __forceinline__ float4 warp_agg2(
    const __half* __restrict__ p_in, const __half* __restrict__ q_in,
    int v0, int v1, int c0, float whe0, float whe1, float b0, float b1)
{
    const float heA = g_he[v0];
    const float heB = g_he[v1];
    float2 pA = __half22float2(*reinterpret_cast<const __half2*>(p_in + v0 * F + c0));
    float2 pB = __half22float2(*reinterpret_cast<const __half2*>(p_in + v1 * F + c0));
    float a0 = pA.x + b0 + whe0 * heA;
    float a1 = pA.y + b1 + whe1 * heA;
    float a2 = pB.x + b0 + whe0 * heB;
    float a3 = pB.y + b1 + whe1 * heB;

    int j0 = g_rowptr[v0];
    const int e0 = g_rowptr[v0 + 1];
    int j1 = g_rowptr[v1];
    const int e1 = g_rowptr[v1 + 1];

    while (j0 + 4 <= e0 && j1 + 4 <= e1) {
        int i0[4], i1[4];
        #pragma unroll
        for (int u = 0; u < 4; u++) i0[u] = g_csr[j0 + u];
        #pragma unroll
        for (int u = 0; u < 4; u++) i1[u] = g_csr[j1 + u];
        float2 f0[4], f1[4];
        #pragma unroll
        for (int u = 0; u < 4; u++)
            f0[u] = __half22float2(*reinterpret_cast<const __half2*>(q_in + i0[u] * F + c0));
        #pragma unroll
        for (int u = 0; u < 4; u++)
            f1[u] = __half22float2(*reinterpret_cast<const __half2*>(q_in + i1[u] * F + c0));
        #pragma unroll
        for (int u = 0; u < 4; u++) { a0 += f0[u].x; a1 += f0[u].y; }
        #pragma unroll
        for (int u = 0; u < 4; u++) { a2 += f1[u].x; a3 += f1[u].y; }
        j0 += 4;
        j1 += 4;
    }
    for (; j0 + 4 <= e0; j0 += 4) {
        int i0[4];
        #pragma unroll
        for (int u = 0; u < 4; u++) i0[u] = g_csr[j0 + u];
        float2 f0[4];
        #pragma unroll
        for (int u = 0; u < 4; u++)
            f0[u] = __half22float2(*reinterpret_cast<const __half2*>(q_in + i0[u] * F + c0));
        #pragma unroll
        for (int u = 0; u < 4; u++) { a0 += f0[u].x; a1 += f0[u].y; }
    }
    for (; j0 < e0; j0++) {
        float2 f = __half22float2(*reinterpret_cast<const __half2*>(q_in + g_csr[j0] * F + c0));
        a0 += f.x;
        a1 += f.y;
    }
    for (; j1 + 4 <= e1; j1 += 4) {
        int i1[4];
        #pragma unroll
        for (int u = 0; u < 4; u++) i1[u] = g_csr[j1 + u];
        float2 f1[4];
        #pragma unroll
        for (int u = 0; u < 4; u++)
            f1[u] = __half22float2(*reinterpret_cast<const __half2*>(q_in + i1[u] * F + c0));
        #pragma unroll
        for (int u = 0; u < 4; u++) { a2 += f1[u].x; a3 += f1[u].y; }
    }
    for (; j1 < e1; j1++) {
        float2 f = __half22float2(*reinterpret_cast<const __half2*>(q_in + g_csr[j1] * F + c0));
        a2 += f.x;
        a3 += f.y;
    }
    return make_float4(a0, a1, a2, a3);
}

// single-node gather (sigmoid/out kernel)
__device__ __forceinline__ float2 warp_agg(
    const __half* __restrict__ p_in, const __half* __restrict__ q_in,
    int v, int c0, float whe0, float whe1, float b0, float b1)
{
    const float he = g_he[v];
    float2 p = __half22float2(*reinterpret_cast<const __half2*>(p_in + v * F + c0));
    float acc0 = p.x + b0 + whe0 * he;
    float acc1 = p.y + b1 + whe1 * he;

    int j = g_rowptr[v];
    const int je = g_rowptr[v + 1];
    for (; j + 8 <= je; j += 8) {
        int idx[8];
        #pragma unroll
        for (int u = 0; u < 8; u++) idx[u] = g_csr[j + u];
        float2 f[8];
        #pragma unroll
        for (int u = 0; u < 8; u++)
            f[u] = __half22float2(*reinterpret_cast<const __half2*>(q_in + idx[u] * F + c0));
        #pragma unroll
        for (int u = 0; u < 8; u++) { acc0 += f[u].x; acc1 += f[u].y; }
    }
    for (; j < je; j++) {
        float2 f = __half22float2(*reinterpret_cast<const __half2*>(q_in + g_csr[j] * F + c0));
        acc0 += f.x;
        acc1 += f.y;
    }
    return make_float2(acc0, acc1);
}

// ---------------- pre: PQ1[v] = W1eff . node_feat[v] --------------------------
__global__ void __launch_bounds__(256) pre_kernel(
    const float* __restrict__ x,
    const __half2* __restrict__ wt,
    __half* __restrict__ p_out, __half* __restrict__ q_out)
{
    __shared__ uint4 sW[K2 * 32];
    const int tid = threadIdx.x;
    for (int i = tid; i < K2 * 32; i += 256)
        sW[i] = reinterpret_cast<const uint4*>(wt)[i];
    __syncthreads();

    const int lane = tid & 31;
    const int gwarp = (blockIdx.x * 256 + tid) >> 5;
    const int nwarps = (NBLK * 256) >> 5;

    for (int pp = gwarp; pp < NN / 2; pp += nwarps) {
        const int v0 = 2 * pp, v1 = v0 + 1;
        float2 x0 = *reinterpret_cast<const float2*>(x + v0 * F + 2 * lane);
        float2 x1 = *reinterpret_cast<const float2*>(x + v1 * F + 2 * lane);
        __half2 h0 = __floats2half2_rn(x0.x, x0.y);
        __half2 h1 = __floats2half2_rn(x1.x, x1.y);
        warp_matvec2(sW, *reinterpret_cast<unsigned*>(&h0),
                     *reinterpret_cast<unsigned*>(&h1), lane, v0, v1, p_out, q_out);
    }
}

// ---------------- fused layer: h = relu(agg(PQ_in)); PQ_out = Wt_next . h -----
__global__ void __launch_bounds__(256, 4) fused_kernel(
    const __half* __restrict__ p_in, const __half* __restrict__ q_in,
    const float* __restrict__ Wcur,
    const float* __restrict__ bias,
    const __half2* __restrict__ wt_next,
    __half* __restrict__ p_out, __half* __restrict__ q_out)
{
    __shared__ uint4 sW[K2 * 32];
    const int tid = threadIdx.x;
    for (int i = tid; i < K2 * 32; i += 256)
        sW[i] = reinterpret_cast<const uint4*>(wt_next)[i];
    __syncthreads();

    const int lane = tid & 31;
    const int c0 = 2 * lane;
    const float whe0 = Wcur[(c0 + 0) * KDIM + 128];
    const float whe1 = Wcur[(c0 + 1) * KDIM + 128];
    const float b0 = bias[c0 + 0];
    const float b1 = bias[c0 + 1];

    const int gwarp = (blockIdx.x * 256 + tid) >> 5;
    const int nwarps = (FNBLK * 256) >> 5;

    for (int pp = gwarp; pp < NN / 2; pp += nwarps) {
        const int v0 = 2 * pp, v1 = v0 + 1;
        float4 a = warp_agg2(p_in, q_in, v0, v1, c0, whe0, whe1, b0, b1);
        __half2 h0 = __floats2half2_rn(fmaxf(a.x, 0.f), fmaxf(a.y, 0.f));
        __half2 h1 = __floats2half2_rn(fmaxf(a.z, 0.f), fmaxf(a.w, 0.f));
        warp_matvec2(sW, *reinterpret_cast<unsigned*>(&h0),
                     *reinterpret_cast<unsigned*>(&h1), lane, v0, v1, p_out, q_out);
    }
}

// ---------------- last hidden (sigmoid) fused with out_pre --------------------
__global__ void __launch_bounds__(256) agg_sigm_out_kernel(
    const __half* __restrict__ p_in, const __half* __restrict__ q_in,
    const float* __restrict__ Wcur,
    const float* __restrict__ bias,
    const float* __restrict__ W2)
{
    const int v    = (blockIdx.x * blockDim.x + threadIdx.x) >> 5;
    const int lane = threadIdx.x & 31;
    if (v >= NN) return;

    const int c0 = 2 * lane;
    const float whe0 = Wcur[(c0 + 0) * KDIM + 128];
    const float whe1 = Wcur[(c0 + 1) * KDIM + 128];

    float2 a = warp_agg(p_in, q_in, v, c0, whe0, whe1, bias[c0], bias[c0 + 1]);
    const float h0 = 1.f / (1.f + __expf(-a.x));
    const float h1 = 1.f / (1.f + __expf(-a.y));

    float p0 = W2[c0] * h0 + W2[c0 + 1] * h1;
    float p1 = W2[KDIM + c0] * h0 + W2[KDIM + c0 + 1] * h1;
    float q0 = W2[64 + c0] * h0 + W2[64 + c0 + 1] * h1;
    float q1 = W2[KDIM + 64 + c0] * h0 + W2[KDIM + 64 + c0 + 1] * h1;

    #pragma unroll
    for (int off = 16; off > 0; off >>= 1) {
        p0 += __shfl_xor_sync(0xffffffffu, p0, off);
        p1 += __shfl_xor_sync(0xffffffffu, p1, off);
        q0 += __shfl_xor_sync(0xffffffffu, q0, off);
        q1 += __shfl_xor_sync(0xffffffffu, q1, off);
    }
    if (lane == 0) {
        g_p2[v] = make_float2(p0, p1);
        g_q2[v] = make_float2(q0, q1);
    }
}

// ---------------- final layer: edge-parallel q2 sum ---------------------------
__global__ void __launch_bounds__(256) out_agg_kernel(
    const float* __restrict__ W2,
    const float* __restrict__ b2,
    float* __restrict__ out)
{
    const int v    = (blockIdx.x * blockDim.x + threadIdx.x) >> 5;
    const int lane = threadIdx.x & 31;
    if (v >= NN) return;

    const int js = g_rowptr[v];
    const int je = g_rowptr[v + 1];
    float acc0 = 0.f, acc1 = 0.f;
    for (int j = js + lane; j < je; j += 32) {
        float2 q = g_q2[g_csr[j]];
        acc0 += q.x;
        acc1 += q.y;
    }
    #pragma unroll
    for (int off = 16; off > 0; off >>= 1) {
        acc0 += __shfl_xor_sync(0xffffffffu, acc0, off);
        acc1 += __shfl_xor_sync(0xffffffffu, acc1, off);
    }
    if (lane == 0) {
        float2 mine = g_p2[v];
        float he = g_he[v];
        out[v * 2 + 0] = mine.x + acc0 + W2[128]        * he + b2[0];
        out[v * 2 + 1] = mine.y + acc1 + W2[KDIM + 128] * he + b2[1];
    }
}

// ---------------- launch ----------------
extern "C" void kernel_launch(void* const* d_in, const int* in_sizes, int n_in,
                              void* d_out, int out_size)
{
    const float* node_feat = (const float*)d_in[0];
    const float* edge_feat = (const float*)d_in[1];
    const int*   src       = (const int*)  d_in[2];
    const int*   dst       = (const int*)  d_in[3];
    const float* W1        = (const float*)d_in[4];
    const float* b1        = (const float*)d_in[5];
    const float* Wmid      = (const float*)d_in[6];
    const float* bmid      = (const float*)d_in[7];
    const float* W2        = (const float*)d_in[8];
    const float* b2        = (const float*)d_in[9];
    float*       out       = (float*)d_out;

    __half *p0, *q0, *p1, *q1;
    __half2* wt;
    void *cnt_ptr, *he_ptr;
    cudaGetSymbolAddress((void**)&p0, g_p0);
    cudaGetSymbolAddress((void**)&q0, g_q0);
    cudaGetSymbolAddress((void**)&p1, g_p1);
    cudaGetSymbolAddress((void**)&q1, g_q1);
    cudaGetSymbolAddress((void**)&wt, g_wt);
    cudaGetSymbolAddress(&cnt_ptr, g_cnt);
    cudaGetSymbolAddress(&he_ptr,  g_he);

    cudaMemsetAsync(cnt_ptr, 0, (NN + 1) * sizeof(int));
    cudaMemsetAsync(he_ptr,  0, NN * sizeof(float));
    hist_kernel<<<(NE + 255) / 256, 256>>>(edge_feat, dst);
    convert_w_kernel<<<(6 * K2 * 128 + 255) / 256, 256>>>(W1, Wmid);
    scan1_kernel<<<SCAN_NBLK, 256>>>();
    scan2_kernel<<<1, 256>>>();
    scan3_kernel<<<SCAN_NBLK, 256>>>();
    scatter_kernel<<<(NE + 255) / 256, 256>>>(src, dst);

    const int WPN_GRID = (NN * 32 + 255) / 256;   // 6250

    pre_kernel<<<NBLK, 256>>>(node_feat, wt + 0 * K2 * 128, p0, q0);
    fused_kernel<<<FNBLK, 256>>>(p0, q0, W1, b1, wt + 1 * K2 * 128, p1, q1);
    fused_kernel<<<FNBLK, 256>>>(p1, q1, Wmid + 0 * F * KDIM, bmid + 0 * F, wt + 2 * K2 * 128, p0, q0);
    fused_kernel<<<FNBLK, 256>>>(p0, q0, Wmid + 1 * F * KDIM, bmid + 1 * F, wt + 3 * K2 * 128, p1, q1);
    fused_kernel<<<FNBLK, 256>>>(p1, q1, Wmid + 2 * F * KDIM, bmid + 2 * F, wt + 4 * K2 * 128, p0, q0);
    fused_kernel<<<FNBLK, 256>>>(p0, q0, Wmid + 3 * F * KDIM, bmid + 3 * F, wt + 5 * K2 * 128, p1, q1);
    agg_sigm_out_kernel<<<WPN_GRID, 256>>>(p1, q1, Wmid + 4 * F * KDIM, bmid + 4 * F, W2);
    out_agg_kernel<<<WPN_GRID, 256>>>(W2, b2, out);
}

// round 17
// speedup vs baseline: 1.3332x; 1.0231x over previous
#include <cuda_runtime.h>
#include <cuda_fp16.h>
#include <cstdint>
#include <math.h>

#define NN 50000
#define NE 800000
#define F 64
#define KDIM 129      // 2*F + 1
#define K2 32         // 64 k's as 32 half2 pairs

#define SCAN_CHUNK 256
#define SCAN_NBLK ((NN + SCAN_CHUNK - 1) / SCAN_CHUNK)   // 196

#define NBLK  (148 * 3)   // persistent grid: pre kernel
#define FNBLK (148 * 5)   // persistent grid: fused kernels (5 blocks/SM)

// ---------------- scratch (static device globals — no allocation) ----------------
__device__ int    g_cnt[NN + 1];
__device__ int    g_rowptr[NN + 1];
__device__ int    g_rank[NE];
__device__ int    g_csr[NE];
__device__ int    g_bsum[SCAN_NBLK];
__device__ int    g_boff[SCAN_NBLK];
__device__ float  g_he[NN];
__device__ __align__(16) __half  g_p0[NN * F];
__device__ __align__(16) __half  g_q0[NN * F];
__device__ __align__(16) __half  g_p1[NN * F];
__device__ __align__(16) __half  g_q1[NN * F];
__device__ __align__(16) __half2 g_wt[6 * K2 * 128];   // [l][k2][n] half2 pairs
__device__ float2 g_p2[NN];
__device__ float2 g_q2[NN];

// ---------------- prologue: CSR build ----------------
__global__ void hist_kernel(const float* __restrict__ ef, const int* __restrict__ dst) {
    int e = blockIdx.x * blockDim.x + threadIdx.x;
    if (e < NE) {
        int d = dst[e];
        g_rank[e] = atomicAdd(&g_cnt[d], 1);
        atomicAdd(&g_he[d], ef[e]);
    }
}

__device__ __forceinline__ int block_incl_scan(int v, int* smem) {
    const int t = threadIdx.x, lane = t & 31, w = t >> 5;
    int incl = v;
    #pragma unroll
    for (int off = 1; off < 32; off <<= 1) {
        int n = __shfl_up_sync(0xffffffffu, incl, off);
        if (lane >= off) incl += n;
    }
    if (lane == 31) smem[w] = incl;
    __syncthreads();
    if (w == 0) {
        int s = (lane < 8) ? smem[lane] : 0;
        #pragma unroll
        for (int off = 1; off < 8; off <<= 1) {
            int n = __shfl_up_sync(0xffffffffu, s, off);
            if (lane >= off) s += n;
        }
        if (lane < 8) smem[lane] = s;
    }
    __syncthreads();
    if (w > 0) incl += smem[w - 1];
    return incl;
}

__global__ void __launch_bounds__(256) scan1_kernel() {
    __shared__ int smem[8];
    int i = blockIdx.x * SCAN_CHUNK + threadIdx.x;
    int v = (i < NN) ? g_cnt[i] : 0;
    int incl = block_incl_scan(v, smem);
    if (threadIdx.x == 255) g_bsum[blockIdx.x] = incl;
}

__global__ void __launch_bounds__(256) scan2_kernel() {
    __shared__ int smem[8];
    int t = threadIdx.x;
    int v = (t < SCAN_NBLK) ? g_bsum[t] : 0;
    int incl = block_incl_scan(v, smem);
    if (t < SCAN_NBLK) g_boff[t] = incl - v;
    if (t == SCAN_NBLK - 1) g_rowptr[NN] = incl;
}

__global__ void __launch_bounds__(256) scan3_kernel() {
    __shared__ int smem[8];
    int i = blockIdx.x * SCAN_CHUNK + threadIdx.x;
    int v = (i < NN) ? g_cnt[i] : 0;
    int incl = block_incl_scan(v, smem);
    if (i < NN) g_rowptr[i] = g_boff[blockIdx.x] + incl - v;
}

__global__ void scatter_kernel(const int* __restrict__ src, const int* __restrict__ dst) {
    int e = blockIdx.x * blockDim.x + threadIdx.x;
    if (e < NE) {
        int d = dst[e];
        g_csr[g_rowptr[d] + g_rank[e]] = src[e];
    }
}

// ---------------- weight repack ----------------
__global__ void convert_w_kernel(const float* __restrict__ W1, const float* __restrict__ Wmid) {
    int idx = blockIdx.x * blockDim.x + threadIdx.x;
    if (idx < 6 * K2 * 128) {
        int l = idx >> 12;
        int rem = idx & 4095;
        int k2 = rem >> 7;
        int n = rem & 127;
        const float* Wl = (l == 0) ? W1 : (Wmid + (l - 1) * F * KDIM);
        int k = 2 * k2;
        float v0, v1;
        if (n < F) { v0 = Wl[n * KDIM + k];            v1 = Wl[n * KDIM + k + 1]; }
        else       { v0 = Wl[(n - F) * KDIM + F + k];  v1 = Wl[(n - F) * KDIM + F + k + 1]; }
        g_wt[idx] = __floats2half2_rn(v0, v1);
    }
}

// ---------------- warp matvec, pure fp16 accumulation (low-reg) ---------------
__device__ __forceinline__ void warp_matvec2h(
    const uint4* __restrict__ sW, unsigned h0u, unsigned h1u,
    int lane, int v0, int v1,
    __half* __restrict__ p_out, __half* __restrict__ q_out)
{
    __half2 a0[4], a1[4];
    #pragma unroll
    for (int j = 0; j < 4; j++) {
        a0[j] = __float2half2_rn(0.f);
        a1[j] = __float2half2_rn(0.f);
    }

    #pragma unroll
    for (int k2 = 0; k2 < K2; k2++) {
        unsigned b0 = __shfl_sync(0xffffffffu, h0u, k2);
        unsigned b1 = __shfl_sync(0xffffffffu, h1u, k2);
        __half2 hb0 = *reinterpret_cast<__half2*>(&b0);
        __half2 hb1 = *reinterpret_cast<__half2*>(&b1);
        uint4 wv = sW[k2 * 32 + lane];
        __half2 w0 = *reinterpret_cast<__half2*>(&wv.x);
        __half2 w1 = *reinterpret_cast<__half2*>(&wv.y);
        __half2 w2 = *reinterpret_cast<__half2*>(&wv.z);
        __half2 w3 = *reinterpret_cast<__half2*>(&wv.w);
        a0[0] = __hfma2(hb0, w0, a0[0]);
        a0[1] = __hfma2(hb0, w1, a0[1]);
        a0[2] = __hfma2(hb0, w2, a0[2]);
        a0[3] = __hfma2(hb0, w3, a0[3]);
        a1[0] = __hfma2(hb1, w0, a1[0]);
        a1[1] = __hfma2(hb1, w1, a1[1]);
        a1[2] = __hfma2(hb1, w2, a1[2]);
        a1[3] = __hfma2(hb1, w3, a1[3]);
    }

    float2 fa0 = __half22float2(a0[0]);
    float2 fb0 = __half22float2(a0[1]);
    float2 fc0 = __half22float2(a0[2]);
    float2 fd0 = __half22float2(a0[3]);
    float2 fa1 = __half22float2(a1[0]);
    float2 fb1 = __half22float2(a1[1]);
    float2 fc1 = __half22float2(a1[2]);
    float2 fd1 = __half22float2(a1[3]);
    __half2 o00 = __floats2half2_rn(fa0.x + fa0.y, fb0.x + fb0.y);
    __half2 o01 = __floats2half2_rn(fc0.x + fc0.y, fd0.x + fd0.y);
    __half2 o10 = __floats2half2_rn(fa1.x + fa1.y, fb1.x + fb1.y);
    __half2 o11 = __floats2half2_rn(fc1.x + fc1.y, fd1.x + fd1.y);
    uint2 u0, u1;
    u0.x = *reinterpret_cast<unsigned*>(&o00);
    u0.y = *reinterpret_cast<unsigned*>(&o01);
    u1.x = *reinterpret_cast<unsigned*>(&o10);
    u1.y = *reinterpret_cast<unsigned*>(&o11);
    if (lane < 16) {
        *reinterpret_cast<uint2*>(p_out + v0 * F + 4 * lane) = u0;
        *reinterpret_cast<uint2*>(p_out + v1 * F + 4 * lane) = u1;
    } else {
        *reinterpret_cast<uint2*>(q_out + v0 * F + 4 * (lane - 16)) = u0;
        *reinterpret_cast<uint2*>(q_out + v1 * F + 4 * (lane - 16)) = u1;
    }
}

// fp32-flush variant (pre kernel; occupancy uncritical there)
__device__ __forceinline__ void warp_matvec2(
    const uint4* __restrict__ sW, unsigned h0u, unsigned h1u,
    int lane, int v0, int v1,
    __half* __restrict__ p_out, __half* __restrict__ q_out)
{
    warp_matvec2h(sW, h0u, h1u, lane, v0, v1, p_out, q_out);
}

// ---------------- interleaved dual-node gather, 4+4 (low-reg) -----------------
__device__ __forceinline__ float4 warp_agg2(
    const __half* __restrict__ p_in, const __half* __restrict__ q_in,
    int v0, int v1, int c0, float whe0, float whe1, float b0, float b1)
{
    const float heA = g_he[v0];
    const float heB = g_he[v1];
    float2 pA = __half22float2(*reinterpret_cast<const __half2*>(p_in + v0 * F + c0));
    float2 pB = __half22float2(*reinterpret_cast<const __half2*>(p_in + v1 * F + c0));
    float a0 = pA.x + b0 + whe0 * heA;
    float a1 = pA.y + b1 + whe1 * heA;
    float a2 = pB.x + b0 + whe0 * heB;
    float a3 = pB.y + b1 + whe1 * heB;

    int j0 = g_rowptr[v0];
    const int e0 = g_rowptr[v0 + 1];
    int j1 = g_rowptr[v1];
    const int e1 = g_rowptr[v1 + 1];

    while (j0 + 4 <= e0 && j1 + 4 <= e1) {
        int i0[4], i1[4];
        #pragma unroll
        for (int u = 0; u < 4; u++) i0[u] = g_csr[j0 + u];
        #pragma unroll
        for (int u = 0; u < 4; u++) i1[u] = g_csr[j1 + u];
        float2 f0[4], f1[4];
        #pragma unroll
        for (int u = 0; u < 4; u++)
            f0[u] = __half22float2(*reinterpret_cast<const __half2*>(q_in + i0[u] * F + c0));
        #pragma unroll
        for (int u = 0; u < 4; u++)
            f1[u] = __half22float2(*reinterpret_cast<const __half2*>(q_in + i1[u] * F + c0));
        #pragma unroll
        for (int u = 0; u < 4; u++) { a0 += f0[u].x; a1 += f0[u].y; }
        #pragma unroll
        for (int u = 0; u < 4; u++) { a2 += f1[u].x; a3 += f1[u].y; }
        j0 += 4;
        j1 += 4;
    }
    for (; j0 + 4 <= e0; j0 += 4) {
        int i0[4];
        #pragma unroll
        for (int u = 0; u < 4; u++) i0[u] = g_csr[j0 + u];
        float2 f0[4];
        #pragma unroll
        for (int u = 0; u < 4; u++)
            f0[u] = __half22float2(*reinterpret_cast<const __half2*>(q_in + i0[u] * F + c0));
        #pragma unroll
        for (int u = 0; u < 4; u++) { a0 += f0[u].x; a1 += f0[u].y; }
    }
    for (; j0 < e0; j0++) {
        float2 f = __half22float2(*reinterpret_cast<const __half2*>(q_in + g_csr[j0] * F + c0));
        a0 += f.x;
        a1 += f.y;
    }
    for (; j1 + 4 <= e1; j1 += 4) {
        int i1[4];
        #pragma unroll
        for (int u = 0; u < 4; u++) i1[u] = g_csr[j1 + u];
        float2 f1[4];
        #pragma unroll
        for (int u = 0; u < 4; u++)
            f1[u] = __half22float2(*reinterpret_cast<const __half2*>(q_in + i1[u] * F + c0));
        #pragma unroll
        for (int u = 0; u < 4; u++) { a2 += f1[u].x; a3 += f1[u].y; }
    }
    for (; j1 < e1; j1++) {
        float2 f = __half22float2(*reinterpret_cast<const __half2*>(q_in + g_csr[j1] * F + c0));
        a2 += f.x;
        a3 += f.y;
    }
    return make_float4(a0, a1, a2, a3);
}

// single-node gather (sigmoid/out kernel)
__device__ __forceinline__ float2 warp_agg(
    const __half* __restrict__ p_in, const __half* __restrict__ q_in,
    int v, int c0, float whe0, float whe1, float b0, float b1)
{
    const float he = g_he[v];
    float2 p = __half22float2(*reinterpret_cast<const __half2*>(p_in + v * F + c0));
    float acc0 = p.x + b0 + whe0 * he;
    float acc1 = p.y + b1 + whe1 * he;

    int j = g_rowptr[v];
    const int je = g_rowptr[v + 1];
    for (; j + 8 <= je; j += 8) {
        int idx[8];
        #pragma unroll
        for (int u = 0; u < 8; u++) idx[u] = g_csr[j + u];
        float2 f[8];
        #pragma unroll
        for (int u = 0; u < 8; u++)
            f[u] = __half22float2(*reinterpret_cast<const __half2*>(q_in + idx[u] * F + c0));
        #pragma unroll
        for (int u = 0; u < 8; u++) { acc0 += f[u].x; acc1 += f[u].y; }
    }
    for (; j < je; j++) {
        float2 f = __half22float2(*reinterpret_cast<const __half2*>(q_in + g_csr[j] * F + c0));
        acc0 += f.x;
        acc1 += f.y;
    }
    return make_float2(acc0, acc1);
}

// ---------------- pre: PQ1[v] = W1eff . node_feat[v] --------------------------
__global__ void __launch_bounds__(256) pre_kernel(
    const float* __restrict__ x,
    const __half2* __restrict__ wt,
    __half* __restrict__ p_out, __half* __restrict__ q_out)
{
    __shared__ uint4 sW[K2 * 32];
    const int tid = threadIdx.x;
    for (int i = tid; i < K2 * 32; i += 256)
        sW[i] = reinterpret_cast<const uint4*>(wt)[i];
    __syncthreads();

    const int lane = tid & 31;
    const int gwarp = (blockIdx.x * 256 + tid) >> 5;
    const int nwarps = (NBLK * 256) >> 5;

    for (int pp = gwarp; pp < NN / 2; pp += nwarps) {
        const int v0 = 2 * pp, v1 = v0 + 1;
        float2 x0 = *reinterpret_cast<const float2*>(x + v0 * F + 2 * lane);
        float2 x1 = *reinterpret_cast<const float2*>(x + v1 * F + 2 * lane);
        __half2 h0 = __floats2half2_rn(x0.x, x0.y);
        __half2 h1 = __floats2half2_rn(x1.x, x1.y);
        warp_matvec2(sW, *reinterpret_cast<unsigned*>(&h0),
                     *reinterpret_cast<unsigned*>(&h1), lane, v0, v1, p_out, q_out);
    }
}

// ---------------- fused layer: h = relu(agg(PQ_in)); PQ_out = Wt_next . h -----
__global__ void __launch_bounds__(256, 5) fused_kernel(
    const __half* __restrict__ p_in, const __half* __restrict__ q_in,
    const float* __restrict__ Wcur,
    const float* __restrict__ bias,
    const __half2* __restrict__ wt_next,
    __half* __restrict__ p_out, __half* __restrict__ q_out)
{
    __shared__ uint4 sW[K2 * 32];
    const int tid = threadIdx.x;
    for (int i = tid; i < K2 * 32; i += 256)
        sW[i] = reinterpret_cast<const uint4*>(wt_next)[i];
    __syncthreads();

    const int lane = tid & 31;
    const int c0 = 2 * lane;
    const float whe0 = Wcur[(c0 + 0) * KDIM + 128];
    const float whe1 = Wcur[(c0 + 1) * KDIM + 128];
    const float b0 = bias[c0 + 0];
    const float b1 = bias[c0 + 1];

    const int gwarp = (blockIdx.x * 256 + tid) >> 5;
    const int nwarps = (FNBLK * 256) >> 5;

    for (int pp = gwarp; pp < NN / 2; pp += nwarps) {
        const int v0 = 2 * pp, v1 = v0 + 1;
        float4 a = warp_agg2(p_in, q_in, v0, v1, c0, whe0, whe1, b0, b1);
        __half2 h0 = __floats2half2_rn(fmaxf(a.x, 0.f), fmaxf(a.y, 0.f));
        __half2 h1 = __floats2half2_rn(fmaxf(a.z, 0.f), fmaxf(a.w, 0.f));
        warp_matvec2h(sW, *reinterpret_cast<unsigned*>(&h0),
                      *reinterpret_cast<unsigned*>(&h1), lane, v0, v1, p_out, q_out);
    }
}

// ---------------- last hidden (sigmoid) fused with out_pre --------------------
__global__ void __launch_bounds__(256) agg_sigm_out_kernel(
    const __half* __restrict__ p_in, const __half* __restrict__ q_in,
    const float* __restrict__ Wcur,
    const float* __restrict__ bias,
    const float* __restrict__ W2)
{
    const int v    = (blockIdx.x * blockDim.x + threadIdx.x) >> 5;
    const int lane = threadIdx.x & 31;
    if (v >= NN) return;

    const int c0 = 2 * lane;
    const float whe0 = Wcur[(c0 + 0) * KDIM + 128];
    const float whe1 = Wcur[(c0 + 1) * KDIM + 128];

    float2 a = warp_agg(p_in, q_in, v, c0, whe0, whe1, bias[c0], bias[c0 + 1]);
    const float h0 = 1.f / (1.f + __expf(-a.x));
    const float h1 = 1.f / (1.f + __expf(-a.y));

    float p0 = W2[c0] * h0 + W2[c0 + 1] * h1;
    float p1 = W2[KDIM + c0] * h0 + W2[KDIM + c0 + 1] * h1;
    float q0 = W2[64 + c0] * h0 + W2[64 + c0 + 1] * h1;
    float q1 = W2[KDIM + 64 + c0] * h0 + W2[KDIM + 64 + c0 + 1] * h1;

    #pragma unroll
    for (int off = 16; off > 0; off >>= 1) {
        p0 += __shfl_xor_sync(0xffffffffu, p0, off);
        p1 += __shfl_xor_sync(0xffffffffu, p1, off);
        q0 += __shfl_xor_sync(0xffffffffu, q0, off);
        q1 += __shfl_xor_sync(0xffffffffu, q1, off);
    }
    if (lane == 0) {
        g_p2[v] = make_float2(p0, p1);
        g_q2[v] = make_float2(q0, q1);
    }
}

// ---------------- final layer: edge-parallel q2 sum ---------------------------
__global__ void __launch_bounds__(256) out_agg_kernel(
    const float* __restrict__ W2,
    const float* __restrict__ b2,
    float* __restrict__ out)
{
    const int v    = (blockIdx.x * blockDim.x + threadIdx.x) >> 5;
    const int lane = threadIdx.x & 31;
    if (v >= NN) return;

    const int js = g_rowptr[v];
    const int je = g_rowptr[v + 1];
    float acc0 = 0.f, acc1 = 0.f;
    for (int j = js + lane; j < je; j += 32) {
        float2 q = g_q2[g_csr[j]];
        acc0 += q.x;
        acc1 += q.y;
    }
    #pragma unroll
    for (int off = 16; off > 0; off >>= 1) {
        acc0 += __shfl_xor_sync(0xffffffffu, acc0, off);
        acc1 += __shfl_xor_sync(0xffffffffu, acc1, off);
    }
    if (lane == 0) {
        float2 mine = g_p2[v];
        float he = g_he[v];
        out[v * 2 + 0] = mine.x + acc0 + W2[128]        * he + b2[0];
        out[v * 2 + 1] = mine.y + acc1 + W2[KDIM + 128] * he + b2[1];
    }
}

// ---------------- launch ----------------
extern "C" void kernel_launch(void* const* d_in, const int* in_sizes, int n_in,
                              void* d_out, int out_size)
{
    const float* node_feat = (const float*)d_in[0];
    const float* edge_feat = (const float*)d_in[1];
    const int*   src       = (const int*)  d_in[2];
    const int*   dst       = (const int*)  d_in[3];
    const float* W1        = (const float*)d_in[4];
    const float* b1        = (const float*)d_in[5];
    const float* Wmid      = (const float*)d_in[6];
    const float* bmid      = (const float*)d_in[7];
    const float* W2        = (const float*)d_in[8];
    const float* b2        = (const float*)d_in[9];
    float*       out       = (float*)d_out;

    __half *p0, *q0, *p1, *q1;
    __half2* wt;
    void *cnt_ptr, *he_ptr;
    cudaGetSymbolAddress((void**)&p0, g_p0);
    cudaGetSymbolAddress((void**)&q0, g_q0);
    cudaGetSymbolAddress((void**)&p1, g_p1);
    cudaGetSymbolAddress((void**)&q1, g_q1);
    cudaGetSymbolAddress((void**)&wt, g_wt);
    cudaGetSymbolAddress(&cnt_ptr, g_cnt);
    cudaGetSymbolAddress(&he_ptr,  g_he);

    cudaMemsetAsync(cnt_ptr, 0, (NN + 1) * sizeof(int));
    cudaMemsetAsync(he_ptr,  0, NN * sizeof(float));
    hist_kernel<<<(NE + 255) / 256, 256>>>(edge_feat, dst);
    convert_w_kernel<<<(6 * K2 * 128 + 255) / 256, 256>>>(W1, Wmid);
    scan1_kernel<<<SCAN_NBLK, 256>>>();
    scan2_kernel<<<1, 256>>>();
    scan3_kernel<<<SCAN_NBLK, 256>>>();
    scatter_kernel<<<(NE + 255) / 256, 256>>>(src, dst);

    const int WPN_GRID = (NN * 32 + 255) / 256;   // 6250

    pre_kernel<<<NBLK, 256>>>(node_feat, wt + 0 * K2 * 128, p0, q0);
    fused_kernel<<<FNBLK, 256>>>(p0, q0, W1, b1, wt + 1 * K2 * 128, p1, q1);
    fused_kernel<<<FNBLK, 256>>>(p1, q1, Wmid + 0 * F * KDIM, bmid + 0 * F, wt + 2 * K2 * 128, p0, q0);
    fused_kernel<<<FNBLK, 256>>>(p0, q0, Wmid + 1 * F * KDIM, bmid + 1 * F, wt + 3 * K2 * 128, p1, q1);
    fused_kernel<<<FNBLK, 256>>>(p1, q1, Wmid + 2 * F * KDIM, bmid + 2 * F, wt + 4 * K2 * 128, p0, q0);
    fused_kernel<<<FNBLK, 256>>>(p0, q0, Wmid + 3 * F * KDIM, bmid + 3 * F, wt + 5 * K2 * 128, p1, q1);
    agg_sigm_out_kernel<<<WPN_GRID, 256>>>(p1, q1, Wmid + 4 * F * KDIM, bmid + 4 * F, W2);
    out_agg_kernel<<<WPN_GRID, 256>>>(W2, b2, out);
}